// round 3
// baseline (speedup 1.0000x reference)
#include <cuda_runtime.h>

// ---------------------------------------------------------------------------
// TimeAwareKAN: out[b,h,n,o] = silu(x_in) @ base_w^T + base_b
//                            + sum_g exp(-(2*(x_in - grid_g))^2) @ spline_w[:,:,g]^T
// x_in = concat(x[b,h,n,:], time_emb[t_indices[h],:])  -> 128 features
// Reformulated as a single GEMM: out[m,o] = sum_{k<768} F[m,k] * W[o,k] + b[o]
//   k = j*128 + i;  j==0: silu;  j=1..5: RBF basis at grid_{j-1}
//
// NOTE: t_indices is int32 on device (JAX x64 is disabled; jnp.int64 request
// silently becomes int32). Reading it as int64 was the round-1 OOB crash.
// ---------------------------------------------------------------------------

#define B_   4
#define H_   24
#define N_   512
#define C_   120
#define D_   128          // C + 8
#define O_   512
#define G_   5
#define M_TOTAL (B_ * H_ * N_)     // 49152
#define K_TOTAL (6 * D_)           // 768

#define BM 128
#define BO 64
#define BK 32
#define THREADS 256

// Packed weight scratch: W2[k][o], k = j*128+i
__device__ float g_W[K_TOTAL * O_];   // 1.5 MB

__global__ void prep_W_kernel(const float* __restrict__ base_w,
                              const float* __restrict__ spline_w) {
    int idx = blockIdx.x * blockDim.x + threadIdx.x;
    if (idx >= K_TOTAL * O_) return;
    int k = idx / O_;
    int o = idx - k * O_;
    int j = k >> 7;          // 0..5
    int i = k & 127;
    float w;
    if (j == 0) w = base_w[o * D_ + i];
    else        w = spline_w[(o * D_ + i) * G_ + (j - 1)];
    g_W[k * O_ + o] = w;
}

__global__ __launch_bounds__(THREADS, 2)
void kan_gemm_kernel(const float* __restrict__ x,
                     const int* __restrict__ t_indices,
                     const float* __restrict__ time_emb,
                     const float* __restrict__ base_b,
                     float* __restrict__ out) {
    extern __shared__ float smem[];
    float* xin = smem;                          // [BM][D_]       128*128
    float* Fs  = xin + BM * D_;                 // [BK][BM+1]     32*129
    float* Ws  = Fs + BK * (BM + 1);            // [BK][BO+4]     32*68

    const int tid = threadIdx.x;
    const int m0  = blockIdx.y * BM;
    const int o0  = blockIdx.x * BO;

    // All BM=128 rows of this block share the same (b,h): 512 % 128 == 0.
    const int h = (m0 / N_) % H_;
    int tsel = t_indices[h];
    if (tsel < 0) tsel = 0;
    if (tsel >= H_) tsel = H_ - 1;

    // ---- Stage x rows into smem (float4, coalesced) ----
    {
        const int vecs_per_row = C_ / 4;        // 30
        for (int idx = tid; idx < BM * vecs_per_row; idx += THREADS) {
            int r  = idx / vecs_per_row;
            int c4 = idx - r * vecs_per_row;
            float4 v = reinterpret_cast<const float4*>(
                x + (size_t)(m0 + r) * C_)[c4];
            float* dst = xin + r * D_ + c4 * 4;
            dst[0] = v.x; dst[1] = v.y; dst[2] = v.z; dst[3] = v.w;
        }
        for (int idx = tid; idx < BM * 8; idx += THREADS) {
            int r = idx >> 3;
            int j = idx & 7;
            xin[r * D_ + C_ + j] = time_emb[tsel * 8 + j];
        }
    }

    float acc[8][4];
#pragma unroll
    for (int u = 0; u < 8; ++u)
#pragma unroll
        for (int v = 0; v < 4; ++v) acc[u][v] = 0.0f;

    const int tx = tid & 15;    // o sub-tile: 16 * 4 = 64
    const int ty = tid >> 4;    // m sub-tile: 16 * 8 = 128

    // ---- K loop over 768 features in chunks of 32 ----
#pragma unroll 1
    for (int kt = 0; kt < K_TOTAL / BK; ++kt) {
        const int k0 = kt * BK;
        const int j  = k0 >> 7;      // feature family (uniform over CTA)
        const int i0 = k0 & 127;

        __syncthreads();   // previous-iteration consumers done

        // Fill feature slab Fs[kk][r]  (each (m,k) computed once per CTA)
        for (int l = tid; l < BM * BK; l += THREADS) {
            int r  = l >> 5;
            int ii = l & 31;
            float v = xin[r * D_ + i0 + ii];
            float f;
            if (j == 0) {
                // silu
                f = __fdividef(v, 1.0f + __expf(-v));
            } else {
                float gc = -1.0f + 0.5f * (float)(j - 1);
                float t2 = (v - gc) * 2.0f;
                f = __expf(-t2 * t2);
            }
            Fs[ii * (BM + 1) + r] = f;
        }

        // Fill weight slab Ws[kk][oo]
        for (int l = tid; l < BK * BO; l += THREADS) {
            int kk = l >> 6;
            int oo = l & 63;
            Ws[kk * (BO + 4) + oo] = g_W[(k0 + kk) * O_ + o0 + oo];
        }

        __syncthreads();

        // ---- inner product ----
#pragma unroll
        for (int kk = 0; kk < BK; ++kk) {
            float a[8];
#pragma unroll
            for (int u = 0; u < 8; ++u)
                a[u] = Fs[kk * (BM + 1) + ty * 8 + u];
            float b[4];
#pragma unroll
            for (int v = 0; v < 4; ++v)
                b[v] = Ws[kk * (BO + 4) + tx * 4 + v];
#pragma unroll
            for (int u = 0; u < 8; ++u)
#pragma unroll
                for (int v = 0; v < 4; ++v)
                    acc[u][v] += a[u] * b[v];
        }
    }

    // ---- epilogue: + base_b, vectorized store ----
    float bb[4];
#pragma unroll
    for (int v = 0; v < 4; ++v)
        bb[v] = __ldg(base_b + o0 + tx * 4 + v);

#pragma unroll
    for (int u = 0; u < 8; ++u) {
        int m = m0 + ty * 8 + u;
        float4 res;
        res.x = acc[u][0] + bb[0];
        res.y = acc[u][1] + bb[1];
        res.z = acc[u][2] + bb[2];
        res.w = acc[u][3] + bb[3];
        reinterpret_cast<float4*>(out + (size_t)m * O_ + o0 + tx * 4)[0] = res;
    }
}

extern "C" void kernel_launch(void* const* d_in, const int* in_sizes, int n_in,
                              void* d_out, int out_size) {
    const float* x         = (const float*)d_in[0];
    const int*   t_indices = (const int*)d_in[1];     // int32! (JAX x64 disabled)
    const float* time_emb  = (const float*)d_in[2];
    const float* base_w    = (const float*)d_in[3];
    const float* base_b    = (const float*)d_in[4];
    const float* spline_w  = (const float*)d_in[5];
    float* out = (float*)d_out;

    // Pack combined weights [768][512]
    {
        int total = K_TOTAL * O_;
        prep_W_kernel<<<(total + 255) / 256, 256>>>(base_w, spline_w);
    }

    // Fused feature + GEMM
    const int smem_bytes =
        (BM * D_ + BK * (BM + 1) + BK * (BO + 4)) * (int)sizeof(float); // ~90.8 KB
    cudaFuncSetAttribute(kan_gemm_kernel,
                         cudaFuncAttributeMaxDynamicSharedMemorySize, smem_bytes);
    dim3 grid(O_ / BO, M_TOTAL / BM);   // (8, 384)
    kan_gemm_kernel<<<grid, THREADS, smem_bytes>>>(x, t_indices, time_emb,
                                                   base_b, out);
}

// round 7
// speedup vs baseline: 2.6184x; 2.6184x over previous
#include <cuda_runtime.h>
#include <cuda_bf16.h>
#include <cstdint>

// ---------------------------------------------------------------------------
// TimeAwareKAN via single GEMM  out[m,o] = sum_k F[m,k] * W[o,k] + b[o]
//   M = 49152, K = 768 (6 families x 128), O = 512
//   family j==0: silu(x_in); j=1..5: exp(-(2*(x_in - g_{j-1}))^2)
// compute_103 (no 'a') toolchain => NO tcgen05. Use warp-level HMMA:
//   mma.sync.aligned.m16n8k16 bf16, hi/lo 3-product split (~1e-5 accuracy),
//   cp.async double-buffered W stream, ldmatrix from SW128-swizzled smem.
// t_indices is int32 on device (JAX x64 disabled).
// ---------------------------------------------------------------------------

#define B_   4
#define H_   24
#define N_   512
#define C_   120
#define D_   128
#define O_   512
#define G_   5
#define M_TOTAL (B_ * H_ * N_)
#define K_TOTAL 768

#define BM 128
#define BN 128
#define KC 64                    // 64 bf16 = 128B rows -> SW128 native
#define NCHUNK (K_TOTAL / KC)    // 12
#define THREADS 256

// SMEM: F bufs 2 x (hi 16KB + lo 16KB) at 0; W bufs 2 x (hi 16KB + lo 16KB)
#define SMEM_W     65536
#define SMEM_BYTES 131072

__device__ __nv_bfloat16 g_W_hi[O_ * K_TOTAL];
__device__ __nv_bfloat16 g_W_lo[O_ * K_TOTAL];

__global__ void prep_W(const float* __restrict__ base_w,
                       const float* __restrict__ spline_w) {
    int idx = blockIdx.x * blockDim.x + threadIdx.x;
    if (idx >= O_ * K_TOTAL) return;
    int n = idx / K_TOTAL, k = idx - n * K_TOTAL;
    int j = k >> 7, i = k & 127;
    float w = (j == 0) ? base_w[n * D_ + i]
                       : spline_w[(n * D_ + i) * G_ + (j - 1)];
    __nv_bfloat16 hi = __float2bfloat16(w);
    float rem = w - __bfloat162float(hi);
    g_W_hi[idx] = hi;
    g_W_lo[idx] = __float2bfloat16(rem);
}

// ---------------- helpers ----------------
__device__ __forceinline__ uint32_t s2u(const void* p) {
    uint32_t a;
    asm("{ .reg .u64 t; cvta.to.shared.u64 t, %1; cvt.u32.u64 %0, t; }"
        : "=r"(a) : "l"(p));
    return a;
}
#define SWZ(o) ((o) ^ (((o) >> 3) & 0x70))

__device__ __forceinline__ void st32(uint32_t a, uint32_t v) {
    asm volatile("st.shared.b32 [%0], %1;" :: "r"(a), "r"(v) : "memory");
}
__device__ __forceinline__ uint32_t pack2(__nv_bfloat16 a, __nv_bfloat16 b) {
    return (uint32_t)__bfloat16_as_ushort(a) |
           ((uint32_t)__bfloat16_as_ushort(b) << 16);
}
__device__ __forceinline__ void ldsm4(uint32_t* r, uint32_t addr) {
    asm volatile("ldmatrix.sync.aligned.m8n8.x4.shared.b16 {%0,%1,%2,%3}, [%4];"
        : "=r"(r[0]), "=r"(r[1]), "=r"(r[2]), "=r"(r[3]) : "r"(addr));
}
__device__ __forceinline__ void mma16816(float* c, const uint32_t* a,
                                         const uint32_t* b) {
    asm volatile(
        "mma.sync.aligned.m16n8k16.row.col.f32.bf16.bf16.f32 "
        "{%0,%1,%2,%3}, {%4,%5,%6,%7}, {%8,%9}, {%0,%1,%2,%3};"
        : "+f"(c[0]), "+f"(c[1]), "+f"(c[2]), "+f"(c[3])
        : "r"(a[0]), "r"(a[1]), "r"(a[2]), "r"(a[3]), "r"(b[0]), "r"(b[1]));
}

// Feature slab for one KC=64 chunk; QB selects which half of the thread's regs.
template <int QB>
__device__ __forceinline__ void do_feats(const float4* xr, int jf, float gc,
                                         int row, int par,
                                         uint32_t fhi, uint32_t flo) {
#pragma unroll
    for (int s = 0; s < 8; ++s) {
        float4 vv = xr[QB + s];
        float fv[4];
        const float* pv = (const float*)&vv;
#pragma unroll
        for (int e = 0; e < 4; ++e) {
            float v = pv[e];
            if (jf == 0) {
                fv[e] = __fdividef(v, 1.0f + __expf(-v));
            } else {
                float t = (v - gc) * 2.0f;
                fv[e] = __expf(-t * t);
            }
        }
        __nv_bfloat16 h0 = __float2bfloat16(fv[0]);
        __nv_bfloat16 h1 = __float2bfloat16(fv[1]);
        __nv_bfloat16 h2 = __float2bfloat16(fv[2]);
        __nv_bfloat16 h3 = __float2bfloat16(fv[3]);
        uint32_t hp0 = pack2(h0, h1), hp1 = pack2(h2, h3);
        __nv_bfloat16 l0 = __float2bfloat16(fv[0] - __bfloat162float(h0));
        __nv_bfloat16 l1 = __float2bfloat16(fv[1] - __bfloat162float(h1));
        __nv_bfloat16 l2 = __float2bfloat16(fv[2] - __bfloat162float(h2));
        __nv_bfloat16 l3 = __float2bfloat16(fv[3] - __bfloat162float(h3));
        uint32_t lp0 = pack2(l0, l1), lp1 = pack2(l2, l3);

        int kk = par * 4 + 8 * s;
        uint32_t off = (uint32_t)(row * 128 + kk * 2);
        uint32_t sa0 = SWZ(off), sa1 = SWZ(off + 4);
        st32(fhi + sa0, hp0);
        st32(fhi + sa1, hp1);
        st32(flo + sa0, lp0);
        st32(flo + sa1, lp1);
    }
}

__global__ __launch_bounds__(THREADS, 1)
void kan_hmma_kernel(const float* __restrict__ x,
                     const int* __restrict__ t_indices,
                     const float* __restrict__ time_emb,
                     const float* __restrict__ base_b,
                     float* __restrict__ out) {
    extern __shared__ char smem[];
    const uint32_t sb = s2u(smem);
    const int tid = threadIdx.x, wid = tid >> 5, lane = tid & 31;
    const int m0 = blockIdx.y * BM, o0 = blockIdx.x * BN;
    const int h = (m0 / N_) % H_;
    int ts = t_indices[h];
    ts = min(max(ts, 0), H_ - 1);

    const int warp_m = wid & 3;        // 4 x 32-row tiles
    const int warp_n = wid >> 2;       // 2 x 64-col tiles

    // ---- x rows -> registers: thread (row = tid/2, par = tid&1) ----
    const int row = tid >> 1, par = tid & 1;
    float4 xr[16];
    {
        const float* xrow = x + (size_t)(m0 + row) * C_;
#pragma unroll
        for (int q = 0; q < 15; ++q)
            xr[q] = *(const float4*)(xrow + par * 4 + q * 8);
        xr[15] = *(const float4*)(time_emb + ts * 8 + par * 4);
    }

    // ---- per-lane ldmatrix address components (SW128) ----
    // A (F) x4: g0 rows+0 klow, g1 rows+8 klow, g2 rows+0 khigh, g3 rows+8 khigh
    const int rowA0 = warp_m * 32 + ((lane >> 3) & 1) * 8 + (lane & 7);
    const int rowA1 = rowA0 + 16;
    const uint32_t kaoff = ((lane >> 4) & 1) * 16;
    const uint32_t aB0 = rowA0 * 128, aX0 = (rowA0 & 7) * 16;
    const uint32_t aB1 = rowA1 * 128, aX1 = (rowA1 & 7) * 16;
    // B (W) x4: g0 rows+0 klow, g1 rows+0 khigh, g2 rows+8 klow, g3 rows+8 khigh
    const int rowBb = warp_n * 64 + ((lane >> 4) & 1) * 8 + (lane & 7);
    const uint32_t kboff = ((lane >> 3) & 1) * 16;
    uint32_t bB[4], bX[4];
#pragma unroll
    for (int ng = 0; ng < 4; ++ng) {
        int r = rowBb + ng * 16;
        bB[ng] = r * 128;
        bX[ng] = (r & 7) * 16;
    }

    float acc[2][8][4];
#pragma unroll
    for (int t = 0; t < 2; ++t)
#pragma unroll
        for (int j = 0; j < 8; ++j)
#pragma unroll
            for (int e = 0; e < 4; ++e) acc[t][j][e] = 0.0f;

    // ---- prologue: W(0) prefetch + feats(0) ----
    auto issue_W = [&](int kt, int buf) {
        const int k0 = kt * KC;
        const uint32_t wbase = sb + SMEM_W + buf * 32768;
#pragma unroll
        for (int s = 0; s < 8; ++s) {
            int v  = tid + THREADS * s;      // 0..2047 16B-units
            int hl = v >> 10;                // 0: hi, 1: lo
            int r  = (v >> 3) & 127;
            int u  = v & 7;
            const __nv_bfloat16* src =
                (hl ? g_W_lo : g_W_hi) + (size_t)(o0 + r) * K_TOTAL + k0 + u * 8;
            uint32_t dst = wbase + hl * 16384 + SWZ((uint32_t)(r * 128 + u * 16));
            asm volatile("cp.async.cg.shared.global [%0], [%1], 16;"
                         :: "r"(dst), "l"(src));
        }
        asm volatile("cp.async.commit_group;" ::: "memory");
    };
    auto do_feats_kt = [&](int kt, int buf) {
        const int jf = kt >> 1;
        const float gc = -1.0f + 0.5f * (float)(jf - 1);
        const uint32_t fhi = sb + buf * 32768;
        const uint32_t flo = fhi + 16384;
        if (kt & 1) do_feats<8>(xr, jf, gc, row, par, fhi, flo);
        else        do_feats<0>(xr, jf, gc, row, par, fhi, flo);
    };

    issue_W(0, 0);
    do_feats_kt(0, 0);
    asm volatile("cp.async.wait_group 0;" ::: "memory");
    __syncthreads();

    // ---- main loop: one __syncthreads per chunk ----
#pragma unroll 1
    for (int kt = 0; kt < NCHUNK; ++kt) {
        const int b = kt & 1;
        if (kt + 1 < NCHUNK) issue_W(kt + 1, b ^ 1);

        const uint32_t fb = sb + b * 32768;        // F hi
        const uint32_t fl = fb + 16384;            // F lo
        const uint32_t wb = sb + SMEM_W + b * 32768;
        const uint32_t wl = wb + 16384;

#pragma unroll
        for (int s = 0; s < 4; ++s) {
            const uint32_t ka = s * 32 + kaoff;
            const uint32_t kb = s * 32 + kboff;
            uint32_t ah0[4], ah1[4], al0[4], al1[4];
            ldsm4(ah0, fb + aB0 + (ka ^ aX0));
            ldsm4(ah1, fb + aB1 + (ka ^ aX1));
            ldsm4(al0, fl + aB0 + (ka ^ aX0));
            ldsm4(al1, fl + aB1 + (ka ^ aX1));
#pragma unroll
            for (int ng = 0; ng < 4; ++ng) {
                uint32_t bh[4], bl[4];
                ldsm4(bh, wb + bB[ng] + (kb ^ bX[ng]));
                ldsm4(bl, wl + bB[ng] + (kb ^ bX[ng]));
                // n8 tile j0 uses {r0,r1}; j1 uses {r2,r3}
                mma16816(acc[0][ng * 2 + 0], ah0, bh + 0);
                mma16816(acc[0][ng * 2 + 0], ah0, bl + 0);
                mma16816(acc[0][ng * 2 + 0], al0, bh + 0);
                mma16816(acc[0][ng * 2 + 1], ah0, bh + 2);
                mma16816(acc[0][ng * 2 + 1], ah0, bl + 2);
                mma16816(acc[0][ng * 2 + 1], al0, bh + 2);
                mma16816(acc[1][ng * 2 + 0], ah1, bh + 0);
                mma16816(acc[1][ng * 2 + 0], ah1, bl + 0);
                mma16816(acc[1][ng * 2 + 0], al1, bh + 0);
                mma16816(acc[1][ng * 2 + 1], ah1, bh + 2);
                mma16816(acc[1][ng * 2 + 1], ah1, bl + 2);
                mma16816(acc[1][ng * 2 + 1], al1, bh + 2);
            }
        }

        if (kt + 1 < NCHUNK) do_feats_kt(kt + 1, b ^ 1);
        asm volatile("cp.async.wait_group 0;" ::: "memory");
        __syncthreads();
    }

    // ---- epilogue: + bias, float2 stores ----
    {
        const float* bb = base_b + o0 + warp_n * 64;
        float2 bi[8];
#pragma unroll
        for (int j = 0; j < 8; ++j)
            bi[j] = *(const float2*)(bb + j * 8 + (lane & 3) * 2);
#pragma unroll
        for (int t = 0; t < 2; ++t) {
            int r0 = m0 + warp_m * 32 + t * 16 + (lane >> 2);
            float* p0 = out + (size_t)r0 * O_ + o0 + warp_n * 64;
            float* p1 = p0 + (size_t)8 * O_;
#pragma unroll
            for (int j = 0; j < 8; ++j) {
                int col = j * 8 + (lane & 3) * 2;
                float2 v0, v1;
                v0.x = acc[t][j][0] + bi[j].x;
                v0.y = acc[t][j][1] + bi[j].y;
                v1.x = acc[t][j][2] + bi[j].x;
                v1.y = acc[t][j][3] + bi[j].y;
                *(float2*)(p0 + col) = v0;
                *(float2*)(p1 + col) = v1;
            }
        }
    }
}

extern "C" void kernel_launch(void* const* d_in, const int* in_sizes, int n_in,
                              void* d_out, int out_size) {
    const float* x         = (const float*)d_in[0];
    const int*   t_indices = (const int*)d_in[1];   // int32 (JAX x64 disabled)
    const float* time_emb  = (const float*)d_in[2];
    const float* base_w    = (const float*)d_in[3];
    const float* base_b    = (const float*)d_in[4];
    const float* spline_w  = (const float*)d_in[5];
    float* out = (float*)d_out;

    {
        int total = O_ * K_TOTAL;
        prep_W<<<(total + 255) / 256, 256>>>(base_w, spline_w);
    }

    cudaFuncSetAttribute(kan_hmma_kernel,
                         cudaFuncAttributeMaxDynamicSharedMemorySize, SMEM_BYTES);
    dim3 grid(O_ / BN, M_TOTAL / BM);   // (4, 384) = 1536 CTAs
    kan_hmma_kernel<<<grid, THREADS, SMEM_BYTES>>>(x, t_indices, time_emb,
                                                   base_b, out);
}